// round 16
// baseline (speedup 1.0000x reference)
#include <cuda_runtime.h>
#include <cuda_fp16.h>
#include <math.h>
#include <stdint.h>

#define BB 8
#define MM 2048
#define FF 128
#define NT 64
#define NITER (MM/NT)   // 32
#define MT 32
#define WSCALE 0.015625f   // 2^-6: folded into cc; cancels in num/den

// ---- scratch ----
__device__ __half g_ht[BB*FF*MM];     // h^T fp16  [b][f][n]
__device__ __half g_wt_hi[FF*FF];     // W^T hi  [fout][fin]
__device__ __half g_wt_lo[FF*FF];     // W^T lo
__device__ float2 g_rpA[BB*MM];       // (e^{s1}, e^{0.2 s1})
__device__ float2 g_rpB[BB*MM];       // (e^{s2}, e^{0.2 s2})

__device__ __forceinline__ void cp_async16(uint32_t dst, const void* src) {
    asm volatile("cp.async.cg.shared.global [%0], [%1], 16;" :: "r"(dst), "l"(src));
}

#define LDSM4(r, addr) \
    asm volatile("ldmatrix.sync.aligned.m8n8.x4.shared.b16 {%0,%1,%2,%3}, [%4];" \
        : "=r"((r)[0]), "=r"((r)[1]), "=r"((r)[2]), "=r"((r)[3]) : "r"(addr))

#define MMAF16(c, a, b0, b1) \
    asm volatile("mma.sync.aligned.m16n8k16.row.col.f32.f16.f16.f32 " \
        "{%0,%1,%2,%3}, {%4,%5,%6,%7}, {%8,%9}, {%0,%1,%2,%3};" \
        : "+f"((c)[0]), "+f"((c)[1]), "+f"((c)[2]), "+f"((c)[3]) \
        : "r"((a)[0]), "r"((a)[1]), "r"((a)[2]), "r"((a)[3]), "r"(b0), "r"(b1))

// ---- K1 SMEM layout (272B rows = 128 halves data + 8 pad) ----
#define SM1_X     0          // x_hi [64][136]h = 17408 ; ht_s reuses [0,18432)
#define SM1_XLO   17408
#define SM1_WT    34816      // Wt_hi [128][136]h = 34816
#define SM1_WTLO  69632
#define SM1_AF    104448     // a[] 256 f32
#define SM1_S1P   105472     // [4][64] f32
#define SM1_S2P   106496
#define SM1_TOT   107520

// ---- K2 SMEM layout (144B rows): w [buf][32x144], h [buf][128x144], den ----
#define W_BUF    4608
#define SM_H     9216
#define H_BUF    18432
#define SM_DEN   46080
#define SM2_TOT  46208

// ---------------------------------------------------------------------------
// K0: W -> W^T fp16 hi/lo in global. 64 blocks x 256.
// ---------------------------------------------------------------------------
__global__ __launch_bounds__(256) void k_wprep(const float* __restrict__ W)
{
    const int o = blockIdx.x*256 + threadIdx.x;   // [fout][fin] linear
    const int n = o >> 7, k = o & 127;
    float v = __ldg(&W[k*FF + n]);
    __half hi = __float2half_rn(v);
    g_wt_hi[o] = hi;
    g_wt_lo[o] = __float2half_rn(v - __half2float(hi));
}

// ---------------------------------------------------------------------------
// K1: h = x@W via 3-pass fp16 mma.sync; fused row stats + h^T fp16 store.
// grid (32, 8), block 256 (8 warps). CTA = 64 m-rows. (unchanged from R15)
// ---------------------------------------------------------------------------
__global__ __launch_bounds__(256) void k_hgemm(const float* __restrict__ x,
                                               const float* __restrict__ a)
{
    extern __shared__ char sm[];
    const uint32_t sbase = (uint32_t)__cvta_generic_to_shared(sm);

    const int b    = blockIdx.y;
    const int m0   = blockIdx.x * 64;
    const int tid  = threadIdx.x;
    const int wid  = tid >> 5;
    const int lane = tid & 31;

    ((float*)(sm + SM1_AF))[tid] = __ldg(&a[tid]);

#pragma unroll
    for (int e = 0; e < 16; e++) {
        int id   = tid + 256*e;
        int comp = id >> 11;
        int cid  = id & 2047;
        int f    = cid >> 4;
        int ch   = cid & 15;
        const __half* src = (comp ? g_wt_lo : g_wt_hi) + f*FF + ch*8;
        cp_async16(sbase + (comp ? SM1_WTLO : SM1_WT) + f*272 + ch*16, src);
    }
    asm volatile("cp.async.commit_group;");

    {
        const float4* xb4 = (const float4*)(x + ((size_t)b*MM + m0)*FF);
        const int row = tid >> 2, kb = tid & 3;
        float4 xv[8];
#pragma unroll
        for (int u = 0; u < 8; u++) xv[u] = __ldg(&xb4[row*32 + kb*8 + u]);
#pragma unroll
        for (int u = 0; u < 8; u++) {
            float4 v = xv[u];
            __half2 h01 = __floats2half2_rn(v.x, v.y);
            __half2 h23 = __floats2half2_rn(v.z, v.w);
            float2 f01 = __half22float2(h01);
            float2 f23 = __half22float2(h23);
            __half2 l01 = __floats2half2_rn(v.x - f01.x, v.y - f01.y);
            __half2 l23 = __floats2half2_rn(v.z - f23.x, v.w - f23.y);
            uint32_t o = sbase + SM1_X + row*272 + kb*64 + u*8;
            asm volatile("st.shared.v2.b32 [%0], {%1,%2};"
                         :: "r"(o), "r"(*(uint32_t*)&h01), "r"(*(uint32_t*)&h23));
            asm volatile("st.shared.v2.b32 [%0], {%1,%2};"
                         :: "r"(o + (SM1_XLO - SM1_X)), "r"(*(uint32_t*)&l01), "r"(*(uint32_t*)&l23));
        }
    }
    asm volatile("cp.async.wait_group 0;");
    __syncthreads();

    const int wm = wid & 1;
    const int wf = wid >> 1;
    const uint32_t offA0 = (uint32_t)((wm*32 + (lane & 7) + ((lane >> 3) & 1)*8)*272
                                      + (lane >> 4)*16);
    const uint32_t offA1 = offA0 + 16*272;
    const uint32_t offB  = (uint32_t)((wf*32 + (lane & 7) + ((lane >= 16) ? 8 : 0))*272
                                      + ((lane >> 3) & 1)*16);
    float C[2][4][4];
#pragma unroll
    for (int i = 0; i < 2; i++)
#pragma unroll
        for (int j = 0; j < 4; j++)
#pragma unroll
            for (int k = 0; k < 4; k++) C[i][j][k] = 0.f;

    const uint32_t xh = sbase + SM1_X,  xl = sbase + SM1_XLO;
    const uint32_t wh = sbase + SM1_WT, wl = sbase + SM1_WTLO;
#pragma unroll
    for (int ks = 0; ks < 8; ks++) {
        uint32_t Ah0[4], Ah1[4], Al0[4], Al1[4];
        LDSM4(Ah0, xh + offA0 + ks*32);
        LDSM4(Ah1, xh + offA1 + ks*32);
        LDSM4(Al0, xl + offA0 + ks*32);
        LDSM4(Al1, xl + offA1 + ks*32);
#pragma unroll
        for (int fs = 0; fs < 2; fs++) {
            uint32_t Bh[4], Bl[4];
            LDSM4(Bh, wh + offB + fs*(16*272) + ks*32);
            LDSM4(Bl, wl + offB + fs*(16*272) + ks*32);
            MMAF16(C[0][2*fs],   Ah0, Bh[0], Bh[1]);
            MMAF16(C[0][2*fs],   Ah0, Bl[0], Bl[1]);
            MMAF16(C[0][2*fs],   Al0, Bh[0], Bh[1]);
            MMAF16(C[0][2*fs+1], Ah0, Bh[2], Bh[3]);
            MMAF16(C[0][2*fs+1], Ah0, Bl[2], Bl[3]);
            MMAF16(C[0][2*fs+1], Al0, Bh[2], Bh[3]);
            MMAF16(C[1][2*fs],   Ah1, Bh[0], Bh[1]);
            MMAF16(C[1][2*fs],   Ah1, Bl[0], Bl[1]);
            MMAF16(C[1][2*fs],   Al1, Bh[0], Bh[1]);
            MMAF16(C[1][2*fs+1], Ah1, Bh[2], Bh[3]);
            MMAF16(C[1][2*fs+1], Ah1, Bl[2], Bl[3]);
            MMAF16(C[1][2*fs+1], Al1, Bh[2], Bh[3]);
        }
    }
    __syncthreads();

    const float* af  = (const float*)(sm + SM1_AF);
    float* s1p = (float*)(sm + SM1_S1P);
    float* s2p = (float*)(sm + SM1_S2P);
    float p1[4] = {0,0,0,0}, p2[4] = {0,0,0,0};
#pragma unroll
    for (int ms = 0; ms < 2; ms++)
#pragma unroll
        for (int j = 0; j < 4; j++) {
            int f0 = wf*32 + j*8 + 2*(lane & 3);
            float a10 = af[f0], a11 = af[f0+1];
            float a20 = af[128+f0], a21 = af[128+f0+1];
            p1[2*ms+0] += C[ms][j][0]*a10 + C[ms][j][1]*a11;
            p1[2*ms+1] += C[ms][j][2]*a10 + C[ms][j][3]*a11;
            p2[2*ms+0] += C[ms][j][0]*a20 + C[ms][j][1]*a21;
            p2[2*ms+1] += C[ms][j][2]*a20 + C[ms][j][3]*a21;
        }
#pragma unroll
    for (int o = 1; o < 4; o <<= 1)
#pragma unroll
        for (int i = 0; i < 4; i++) {
            p1[i] += __shfl_xor_sync(0xffffffffu, p1[i], o, 4);
            p2[i] += __shfl_xor_sync(0xffffffffu, p2[i], o, 4);
        }
    if ((lane & 3) == 0) {
#pragma unroll
        for (int ms = 0; ms < 2; ms++)
#pragma unroll
            for (int i = 0; i < 2; i++) {
                int m = wm*32 + ms*16 + (lane >> 2) + 8*i;
                s1p[wf*64 + m] = p1[2*ms+i];
                s2p[wf*64 + m] = p2[2*ms+i];
            }
    }

#pragma unroll
    for (int ms = 0; ms < 2; ms++)
#pragma unroll
        for (int j = 0; j < 4; j++) {
            int f0 = wf*32 + j*8 + 2*(lane & 3);
            int R0 = wm*32 + ms*16 + (lane >> 2);
            uint16_t v00 = __half_as_ushort(__float2half_rn(C[ms][j][0]));
            uint16_t v01 = __half_as_ushort(__float2half_rn(C[ms][j][1]));
            uint16_t v10 = __half_as_ushort(__float2half_rn(C[ms][j][2]));
            uint16_t v11 = __half_as_ushort(__float2half_rn(C[ms][j][3]));
            asm volatile("st.shared.b16 [%0], %1;" :: "r"(sbase + f0*144 + R0*2), "h"(v00));
            asm volatile("st.shared.b16 [%0], %1;" :: "r"(sbase + (f0+1)*144 + R0*2), "h"(v01));
            asm volatile("st.shared.b16 [%0], %1;" :: "r"(sbase + f0*144 + (R0+8)*2), "h"(v10));
            asm volatile("st.shared.b16 [%0], %1;" :: "r"(sbase + (f0+1)*144 + (R0+8)*2), "h"(v11));
        }
    __syncthreads();

    if (tid < 64) {
        int m = tid;
        float s1 = (s1p[m] + s1p[64+m]) + (s1p[128+m] + s1p[192+m]);
        float s2 = (s2p[m] + s2p[64+m]) + (s2p[128+m] + s2p[192+m]);
        g_rpA[(size_t)b*MM + m0 + m] = make_float2(expf(s1), expf(0.2f*s1));
        g_rpB[(size_t)b*MM + m0 + m] = make_float2(expf(s2), expf(0.2f*s2));
    }

    {
        int f = tid >> 1, hp = tid & 1;
        uint4* dst = (uint4*)((char*)g_ht + (((size_t)b*FF + f)*MM + m0 + hp*32)*2);
#pragma unroll
        for (int q = 0; q < 4; q++)
            dst[q] = *(uint4*)(sm + f*144 + hp*64 + q*16);
    }
}

// ---------------------------------------------------------------------------
// stage one 64-n h tile: 1024 x 16B chunks, 8 per thread (128 threads).
// ---------------------------------------------------------------------------
__device__ __forceinline__ void stage_h(uint32_t hdst, int b, int n0, int tid)
{
#pragma unroll
    for (int e = 0; e < 8; e++) {
        int id    = tid + 128*e;       // 0..1023
        int f     = id >> 3;
        int chunk = id & 7;
        const char* src = (const char*)g_ht + (((size_t)b*FF + f)*MM + n0 + chunk*8) * 2;
        cp_async16(hdst + f*144 + chunk*16, src);
    }
    asm volatile("cp.async.commit_group;");
}

// ---------------------------------------------------------------------------
// K2: fused masked attention, fp16 1-pass MMA, interleaved build/MMA.
// grid (64, 8) = 512 CTAs, block 128 (4 warps), 4 CTAs/SM. CTA = 32 m x 128 f.
// Build map: pc = tid&15 (n quad), pr = tid>>4 -> rows {pr+8i, i<4}.
// MMA map: wm = wid&1 (16 m), wf = wid>>1 (64 f).
// ---------------------------------------------------------------------------
__global__ __launch_bounds__(128, 4) void k_attn(const int* __restrict__ adj,
                                                 float* __restrict__ out)
{
    extern __shared__ char sm[];
    const uint32_t sbase = (uint32_t)__cvta_generic_to_shared(sm);
    float* den_s = (float*)(sm + SM_DEN);

    const int b    = blockIdx.y;
    const int m0   = blockIdx.x * MT;
    const int tid  = threadIdx.x;
    const int wid  = tid >> 5;
    const int lane = tid & 31;

    const int pc = tid & 15;
    const int pr = tid >> 4;   // 0..7

    float2 cc[4];
    float denp[4] = {0.f, 0.f, 0.f, 0.f};
    int4 adjv[4];
    const int* adjp = adj + ((size_t)(b*MM + m0 + pr))*MM + pc*4;
#pragma unroll
    for (int i = 0; i < 4; i++) {
        float2 c = __ldg(&g_rpA[(size_t)b*MM + m0 + pr + 8*i]);
        cc[i] = make_float2(c.x * WSCALE, c.y * WSCALE);
        adjv[i] = __ldg((const int4*)(adjp + (size_t)8*i*MM));
    }

    const int wm = wid & 1;
    const int wf = wid >> 1;
    const uint32_t offA = (uint32_t)((wm*16 + (lane & 7) + ((lane >> 3) & 1)*8)*144
                                     + (lane >> 4)*16);
    const uint32_t offB = (uint32_t)((wf*64 + (lane & 7) + ((lane >= 16) ? 8 : 0))*144
                                     + ((lane >> 3) & 1)*16);
    float C[8][4];
#pragma unroll
    for (int j = 0; j < 8; j++)
#pragma unroll
        for (int k = 0; k < 4; k++) C[j][k] = 0.f;

    auto build_w = [&](int tt) {
        const uint32_t wbase = sbase + (tt & 1)*W_BUF;
        const float4* rb = (const float4*)(g_rpB + (size_t)b*MM + tt*NT) + pc*2;
        float4 v0 = __ldg(rb), v1 = __ldg(rb + 1);
#pragma unroll
        for (int i = 0; i < 4; i++) {
            int4 av = adjv[i];
            int row = pr + 8*i;
            float w0 = av.x ? fmaxf(cc[i].x*v0.x, cc[i].y*v0.y) : 0.f;
            float w1 = av.y ? fmaxf(cc[i].x*v0.z, cc[i].y*v0.w) : 0.f;
            float w2 = av.z ? fmaxf(cc[i].x*v1.x, cc[i].y*v1.y) : 0.f;
            float w3 = av.w ? fmaxf(cc[i].x*v1.z, cc[i].y*v1.w) : 0.f;
            __half2 q01 = __floats2half2_rn(w0, w1);
            __half2 q23 = __floats2half2_rn(w2, w3);
            float2 f01 = __half22float2(q01);
            float2 f23 = __half22float2(q23);
            denp[i] += (f01.x + f01.y) + (f23.x + f23.y);
            uint32_t u0 = *(uint32_t*)&q01;
            uint32_t u1 = *(uint32_t*)&q23;
            uint32_t o = wbase + row*144 + pc*8;
            asm volatile("st.shared.v2.b32 [%0], {%1,%2};" :: "r"(o), "r"(u0), "r"(u1));
        }
    };

    auto prefetch_adj = [&](int tt) {
        const int tn = (tt < NITER) ? tt*NT : 0;
#pragma unroll
        for (int i = 0; i < 4; i++)
            adjv[i] = __ldg((const int4*)(adjp + (size_t)8*i*MM + tn));
    };

    auto do_mma = [&](int tt) {
        const uint32_t wbase = sbase + (tt & 1)*W_BUF;
        const uint32_t hbase = sbase + SM_H + (tt & 1)*H_BUF;
#pragma unroll
        for (int ks = 0; ks < 4; ks++) {
            uint32_t A[4];
            LDSM4(A, wbase + offA + ks*32);
#pragma unroll
            for (int fs = 0; fs < 4; fs++) {
                uint32_t B[4];
                LDSM4(B, hbase + offB + fs*(16*144) + ks*32);
                MMAF16(C[2*fs],   A, B[0], B[1]);
                MMAF16(C[2*fs+1], A, B[2], B[3]);
            }
        }
    };

    stage_h(sbase + SM_H, b, 0, tid);
    build_w(0);
    prefetch_adj(1);
    asm volatile("cp.async.wait_group 0;");
    __syncthreads();

    for (int t = 0; t < NITER; t++) {
        const bool more = (t + 1 < NITER);
        if (more)
            stage_h(sbase + SM_H + ((t+1) & 1)*H_BUF, b, (t+1)*NT, tid);
        if (wid & 1) {
            if (more) { build_w(t+1); prefetch_adj(t+2); }
            do_mma(t);
        } else {
            do_mma(t);
            if (more) { build_w(t+1); prefetch_adj(t+2); }
        }
        if (more)
            asm volatile("cp.async.wait_group 0;");
        __syncthreads();
    }

    // den reduce over the 16 pc-lanes sharing each row group
#pragma unroll
    for (int i = 0; i < 4; i++)
#pragma unroll
        for (int o = 8; o > 0; o >>= 1)
            denp[i] += __shfl_down_sync(0xffffffffu, denp[i], o, 16);
    if (pc == 0) {
#pragma unroll
        for (int i = 0; i < 4; i++) den_s[pr + 8*i] = denp[i];
    }
    __syncthreads();

    // epilogue: normalize + ELU + store
    float* ob = out + ((size_t)b*MM + m0) * FF;
    const int R0 = wm*16 + (lane >> 2);
    const float inv0 = 1.0f / den_s[R0];
    const float inv1 = 1.0f / den_s[R0 + 8];
#pragma unroll
    for (int j = 0; j < 8; j++) {
        int f0 = wf*64 + j*8 + 2*(lane & 3);
        float e0 = C[j][0] * inv0;
        float e1 = C[j][1] * inv0;
        float e2 = C[j][2] * inv1;
        float e3 = C[j][3] * inv1;
        e0 = e0 > 0.f ? e0 : expm1f(e0);
        e1 = e1 > 0.f ? e1 : expm1f(e1);
        e2 = e2 > 0.f ? e2 : expm1f(e2);
        e3 = e3 > 0.f ? e3 : expm1f(e3);
        *(float2*)(ob + (size_t)R0*FF + f0)     = make_float2(e0, e1);
        *(float2*)(ob + (size_t)(R0+8)*FF + f0) = make_float2(e2, e3);
    }
}

extern "C" void kernel_launch(void* const* d_in, const int* in_sizes, int n_in,
                              void* d_out, int out_size)
{
    const float* x   = (const float*)d_in[0];
    const int*   adj = (const int*)d_in[1];
    const float* W   = (const float*)d_in[2];
    const float* a   = (const float*)d_in[3];
    float*       out = (float*)d_out;

    static int smem_set = 0;
    if (!smem_set) {
        cudaFuncSetAttribute(k_hgemm, cudaFuncAttributeMaxDynamicSharedMemorySize, SM1_TOT);
        cudaFuncSetAttribute(k_attn,  cudaFuncAttributeMaxDynamicSharedMemorySize, SM2_TOT);
        smem_set = 1;
    }

    k_wprep<<<FF*FF/256, 256>>>(W);
    k_hgemm<<<dim3(MM/64, BB), 256, SM1_TOT>>>(x, a);
    k_attn<<<dim3(MM/MT, BB), 128, SM2_TOT>>>(adj, out);
}

// round 17
// speedup vs baseline: 1.1051x; 1.1051x over previous
#include <cuda_runtime.h>
#include <cuda_fp16.h>
#include <math.h>
#include <stdint.h>

#define BB 8
#define MM 2048
#define FF 128
#define NT 64
#define NITER (MM/NT)   // 32
#define MT 64
#define WSCALE 0.015625f   // 2^-6: folded into cc; cancels in num/den

// ---- scratch ----
__device__ __half g_ht[BB*FF*MM];     // h^T fp16  [b][f][n]
__device__ float2 g_rpA[BB*MM];       // (e^{s1}, e^{0.2 s1})
__device__ float2 g_rpB[BB*MM];       // (e^{s2}, e^{0.2 s2})

__device__ __forceinline__ void cp_async16(uint32_t dst, const void* src) {
    asm volatile("cp.async.cg.shared.global [%0], [%1], 16;" :: "r"(dst), "l"(src));
}

#define LDSM4(r, addr) \
    asm volatile("ldmatrix.sync.aligned.m8n8.x4.shared.b16 {%0,%1,%2,%3}, [%4];" \
        : "=r"((r)[0]), "=r"((r)[1]), "=r"((r)[2]), "=r"((r)[3]) : "r"(addr))

#define LDSM4T(r, addr) \
    asm volatile("ldmatrix.sync.aligned.m8n8.x4.trans.shared.b16 {%0,%1,%2,%3}, [%4];" \
        : "=r"((r)[0]), "=r"((r)[1]), "=r"((r)[2]), "=r"((r)[3]) : "r"(addr))

#define MMAF16(c, a, b0, b1) \
    asm volatile("mma.sync.aligned.m16n8k16.row.col.f32.f16.f16.f32 " \
        "{%0,%1,%2,%3}, {%4,%5,%6,%7}, {%8,%9}, {%0,%1,%2,%3};" \
        : "+f"((c)[0]), "+f"((c)[1]), "+f"((c)[2]), "+f"((c)[3]) \
        : "r"((a)[0]), "r"((a)[1]), "r"((a)[2]), "r"((a)[3]), "r"(b0), "r"(b1))

// ---- K1 SMEM layout (272B rows = 128 halves data + 8 pad) ----
#define SM1_X     0          // x_hi [64][136]h ; ht_s reuses [0,18432)
#define SM1_XLO   17408
#define SM1_WT    34816      // W hi [128 k][136 n]h  (native [fin][fout])
#define SM1_WTLO  69632
#define SM1_AF    104448     // a[] 256 f32
#define SM1_S1P   105472     // [4][64] f32
#define SM1_S2P   106496
#define SM1_TOT   107520

// ---- K2 SMEM layout (144B rows) ----
#define W_BUF    9216
#define SM_H     18432
#define H_BUF    18432
#define SM_DEN   55296
#define SM2_TOT  55552

// ---------------------------------------------------------------------------
// K1: h = x@W via 3-pass fp16 mma.sync; fused W conversion (no k_wprep),
// fused row stats + h^T fp16 store. grid (32, 8), block 256. CTA = 64 m-rows.
// ---------------------------------------------------------------------------
__global__ __launch_bounds__(256) void k_hgemm(const float* __restrict__ x,
                                               const float* __restrict__ W,
                                               const float* __restrict__ a)
{
    extern __shared__ char sm[];
    const uint32_t sbase = (uint32_t)__cvta_generic_to_shared(sm);

    const int b    = blockIdx.y;
    const int m0   = blockIdx.x * 64;
    const int tid  = threadIdx.x;
    const int wid  = tid >> 5;
    const int lane = tid & 31;

    ((float*)(sm + SM1_AF))[tid] = __ldg(&a[tid]);

    // stage W fp32 -> fp16 hi/lo in native [k][n] layout (conflict-free)
#pragma unroll
    for (int p = 0; p < 16; p++) {
        int lin = tid + 256*p;
        int k   = lin >> 5;
        int n0  = (lin & 31) * 4;
        float4 v = __ldg((const float4*)(W + k*FF + n0));
        __half hx = __float2half_rn(v.x), hy = __float2half_rn(v.y);
        __half hz = __float2half_rn(v.z), hw = __float2half_rn(v.w);
        uint32_t h01 = (uint32_t)__half_as_ushort(hx) | ((uint32_t)__half_as_ushort(hy) << 16);
        uint32_t h23 = (uint32_t)__half_as_ushort(hz) | ((uint32_t)__half_as_ushort(hw) << 16);
        __half2 l01 = __floats2half2_rn(v.x - __half2float(hx), v.y - __half2float(hy));
        __half2 l23 = __floats2half2_rn(v.z - __half2float(hz), v.w - __half2float(hw));
        uint32_t o = sbase + SM1_WT + k*272 + n0*2;
        asm volatile("st.shared.v2.b32 [%0], {%1,%2};" :: "r"(o), "r"(h01), "r"(h23));
        asm volatile("st.shared.v2.b32 [%0], {%1,%2};"
                     :: "r"(o + (SM1_WTLO - SM1_WT)), "r"(*(uint32_t*)&l01), "r"(*(uint32_t*)&l23));
    }

    // load + convert x tile (64 x 128 fp32): row = tid>>2, kb = tid&3
    {
        const float4* xb4 = (const float4*)(x + ((size_t)b*MM + m0)*FF);
        const int row = tid >> 2, kb = tid & 3;
        float4 xv[8];
#pragma unroll
        for (int u = 0; u < 8; u++) xv[u] = __ldg(&xb4[row*32 + kb*8 + u]);
#pragma unroll
        for (int u = 0; u < 8; u++) {
            float4 v = xv[u];
            __half2 h01 = __floats2half2_rn(v.x, v.y);
            __half2 h23 = __floats2half2_rn(v.z, v.w);
            float2 f01 = __half22float2(h01);
            float2 f23 = __half22float2(h23);
            __half2 l01 = __floats2half2_rn(v.x - f01.x, v.y - f01.y);
            __half2 l23 = __floats2half2_rn(v.z - f23.x, v.w - f23.y);
            uint32_t o = sbase + SM1_X + row*272 + kb*64 + u*8;
            asm volatile("st.shared.v2.b32 [%0], {%1,%2};"
                         :: "r"(o), "r"(*(uint32_t*)&h01), "r"(*(uint32_t*)&h23));
            asm volatile("st.shared.v2.b32 [%0], {%1,%2};"
                         :: "r"(o + (SM1_XLO - SM1_X)), "r"(*(uint32_t*)&l01), "r"(*(uint32_t*)&l23));
        }
    }
    __syncthreads();

    // 3-pass MMA: C = x_hi*W_hi + x_hi*W_lo + x_lo*W_hi
    const int wm = wid & 1;
    const int wf = wid >> 1;
    const uint32_t offA0 = (uint32_t)((wm*32 + (lane & 7) + ((lane >> 3) & 1)*8)*272
                                      + (lane >> 4)*16);
    const uint32_t offA1 = offA0 + 16*272;
    // trans B from [k][n]: lane -> k-row (lane&15), n-block ((lane>>4)*8)
    const uint32_t offBt = (uint32_t)((lane & 15)*272 + (lane >> 4)*16);
    float C[2][4][4];
#pragma unroll
    for (int i = 0; i < 2; i++)
#pragma unroll
        for (int j = 0; j < 4; j++)
#pragma unroll
            for (int k = 0; k < 4; k++) C[i][j][k] = 0.f;

    const uint32_t xh = sbase + SM1_X,  xl = sbase + SM1_XLO;
    const uint32_t wh = sbase + SM1_WT, wl = sbase + SM1_WTLO;
#pragma unroll
    for (int ks = 0; ks < 8; ks++) {
        uint32_t Ah0[4], Ah1[4], Al0[4], Al1[4];
        LDSM4(Ah0, xh + offA0 + ks*32);
        LDSM4(Ah1, xh + offA1 + ks*32);
        LDSM4(Al0, xl + offA0 + ks*32);
        LDSM4(Al1, xl + offA1 + ks*32);
#pragma unroll
        for (int fs = 0; fs < 2; fs++) {
            uint32_t Bh[4], Bl[4];
            uint32_t bb = offBt + ks*16*272 + (wf*32 + fs*16)*2;
            LDSM4T(Bh, wh + bb);
            LDSM4T(Bl, wl + bb);
            MMAF16(C[0][2*fs],   Ah0, Bh[0], Bh[1]);
            MMAF16(C[0][2*fs],   Ah0, Bl[0], Bl[1]);
            MMAF16(C[0][2*fs],   Al0, Bh[0], Bh[1]);
            MMAF16(C[0][2*fs+1], Ah0, Bh[2], Bh[3]);
            MMAF16(C[0][2*fs+1], Ah0, Bl[2], Bl[3]);
            MMAF16(C[0][2*fs+1], Al0, Bh[2], Bh[3]);
            MMAF16(C[1][2*fs],   Ah1, Bh[0], Bh[1]);
            MMAF16(C[1][2*fs],   Ah1, Bl[0], Bl[1]);
            MMAF16(C[1][2*fs],   Al1, Bh[0], Bh[1]);
            MMAF16(C[1][2*fs+1], Ah1, Bh[2], Bh[3]);
            MMAF16(C[1][2*fs+1], Ah1, Bl[2], Bl[3]);
            MMAF16(C[1][2*fs+1], Al1, Bh[2], Bh[3]);
        }
    }
    __syncthreads();   // x/W smem dead; safe to reuse for ht_s

    // row stats partials
    const float* af  = (const float*)(sm + SM1_AF);
    float* s1p = (float*)(sm + SM1_S1P);
    float* s2p = (float*)(sm + SM1_S2P);
    float p1[4] = {0,0,0,0}, p2[4] = {0,0,0,0};
#pragma unroll
    for (int ms = 0; ms < 2; ms++)
#pragma unroll
        for (int j = 0; j < 4; j++) {
            int f0 = wf*32 + j*8 + 2*(lane & 3);
            float a10 = af[f0], a11 = af[f0+1];
            float a20 = af[128+f0], a21 = af[128+f0+1];
            p1[2*ms+0] += C[ms][j][0]*a10 + C[ms][j][1]*a11;
            p1[2*ms+1] += C[ms][j][2]*a10 + C[ms][j][3]*a11;
            p2[2*ms+0] += C[ms][j][0]*a20 + C[ms][j][1]*a21;
            p2[2*ms+1] += C[ms][j][2]*a20 + C[ms][j][3]*a21;
        }
#pragma unroll
    for (int o = 1; o < 4; o <<= 1)
#pragma unroll
        for (int i = 0; i < 4; i++) {
            p1[i] += __shfl_xor_sync(0xffffffffu, p1[i], o, 4);
            p2[i] += __shfl_xor_sync(0xffffffffu, p2[i], o, 4);
        }
    if ((lane & 3) == 0) {
#pragma unroll
        for (int ms = 0; ms < 2; ms++)
#pragma unroll
            for (int i = 0; i < 2; i++) {
                int m = wm*32 + ms*16 + (lane >> 2) + 8*i;
                s1p[wf*64 + m] = p1[2*ms+i];
                s2p[wf*64 + m] = p2[2*ms+i];
            }
    }

    // h -> fp16 transpose stage: ht_s[f][m], 144B rows, at smem offset 0
#pragma unroll
    for (int ms = 0; ms < 2; ms++)
#pragma unroll
        for (int j = 0; j < 4; j++) {
            int f0 = wf*32 + j*8 + 2*(lane & 3);
            int R0 = wm*32 + ms*16 + (lane >> 2);
            uint16_t v00 = __half_as_ushort(__float2half_rn(C[ms][j][0]));
            uint16_t v01 = __half_as_ushort(__float2half_rn(C[ms][j][1]));
            uint16_t v10 = __half_as_ushort(__float2half_rn(C[ms][j][2]));
            uint16_t v11 = __half_as_ushort(__float2half_rn(C[ms][j][3]));
            asm volatile("st.shared.b16 [%0], %1;" :: "r"(sbase + f0*144 + R0*2), "h"(v00));
            asm volatile("st.shared.b16 [%0], %1;" :: "r"(sbase + (f0+1)*144 + R0*2), "h"(v01));
            asm volatile("st.shared.b16 [%0], %1;" :: "r"(sbase + f0*144 + (R0+8)*2), "h"(v10));
            asm volatile("st.shared.b16 [%0], %1;" :: "r"(sbase + (f0+1)*144 + (R0+8)*2), "h"(v11));
        }
    __syncthreads();

    // finalize exps
    if (tid < 64) {
        int m = tid;
        float s1 = (s1p[m] + s1p[64+m]) + (s1p[128+m] + s1p[192+m]);
        float s2 = (s2p[m] + s2p[64+m]) + (s2p[128+m] + s2p[192+m]);
        g_rpA[(size_t)b*MM + m0 + m] = make_float2(expf(s1), expf(0.2f*s1));
        g_rpB[(size_t)b*MM + m0 + m] = make_float2(expf(s2), expf(0.2f*s2));
    }

    // coalesced ht_s -> g_ht
    {
        int f = tid >> 1, hp = tid & 1;
        uint4* dst = (uint4*)((char*)g_ht + (((size_t)b*FF + f)*MM + m0 + hp*32)*2);
#pragma unroll
        for (int q = 0; q < 4; q++)
            dst[q] = *(uint4*)(sm + f*144 + hp*64 + q*16);
    }
}

// ---------------------------------------------------------------------------
// stage one 64-n h tile: 1024 x 16B chunks, 4 per thread (256 threads).
// ---------------------------------------------------------------------------
__device__ __forceinline__ void stage_h(uint32_t hdst, int b, int n0, int tid)
{
#pragma unroll
    for (int e = 0; e < 4; e++) {
        int id    = tid + 256*e;       // 0..1023
        int f     = id >> 3;
        int chunk = id & 7;
        const char* src = (const char*)g_ht + (((size_t)b*FF + f)*MM + n0 + chunk*8) * 2;
        cp_async16(hdst + f*144 + chunk*16, src);
    }
    asm volatile("cp.async.commit_group;");
}

// ---------------------------------------------------------------------------
// K2: fused masked attention, fp16 1-pass MMA, interleaved build/MMA.
// grid (32, 8), block 256 (8 warps), 2 CTAs/SM. CTA = 64 m x 128 f, NT=64.
// ---------------------------------------------------------------------------
__global__ __launch_bounds__(256, 2) void k_attn(const int* __restrict__ adj,
                                                 float* __restrict__ out)
{
    extern __shared__ char sm[];
    const uint32_t sbase = (uint32_t)__cvta_generic_to_shared(sm);
    float* den_s = (float*)(sm + SM_DEN);

    const int b    = blockIdx.y;
    const int m0   = blockIdx.x * MT;
    const int tid  = threadIdx.x;
    const int wid  = tid >> 5;
    const int lane = tid & 31;

    const int pc = tid & 15;
    const int pr = tid >> 4;

    float2 cc[4];
    float denp[4] = {0.f, 0.f, 0.f, 0.f};
    int4 adjv[4];
    const int* adjp = adj + ((size_t)(b*MM + m0 + pr))*MM + pc*4;
#pragma unroll
    for (int i = 0; i < 4; i++) {
        float2 c = __ldg(&g_rpA[(size_t)b*MM + m0 + pr + 16*i]);
        cc[i] = make_float2(c.x * WSCALE, c.y * WSCALE);
        adjv[i] = __ldg((const int4*)(adjp + (size_t)16*i*MM));
    }

    const int wm = wid & 1;
    const int wf = wid >> 1;
    const uint32_t offA0 = (uint32_t)((wm*32 + (lane & 7) + ((lane >> 3) & 1)*8)*144
                                      + (lane >> 4)*16);
    const uint32_t offA1 = offA0 + 16*144;
    const uint32_t offB  = (uint32_t)((wf*32 + (lane & 7) + ((lane >= 16) ? 8 : 0))*144
                                      + ((lane >> 3) & 1)*16);
    float C[2][4][4];
#pragma unroll
    for (int i = 0; i < 2; i++)
#pragma unroll
        for (int j = 0; j < 4; j++)
#pragma unroll
            for (int k = 0; k < 4; k++) C[i][j][k] = 0.f;

    auto build_w = [&](int tt) {
        const uint32_t wbase = sbase + (tt & 1)*W_BUF;
        const float4* rb = (const float4*)(g_rpB + (size_t)b*MM + tt*NT) + pc*2;
        float4 v0 = __ldg(rb), v1 = __ldg(rb + 1);
#pragma unroll
        for (int i = 0; i < 4; i++) {
            int4 av = adjv[i];
            int row = pr + 16*i;
            float w0 = av.x ? fmaxf(cc[i].x*v0.x, cc[i].y*v0.y) : 0.f;
            float w1 = av.y ? fmaxf(cc[i].x*v0.z, cc[i].y*v0.w) : 0.f;
            float w2 = av.z ? fmaxf(cc[i].x*v1.x, cc[i].y*v1.y) : 0.f;
            float w3 = av.w ? fmaxf(cc[i].x*v1.z, cc[i].y*v1.w) : 0.f;
            // den from raw fp32 w (quantization mismatch ~2^-12, averages out)
            denp[i] += (w0 + w1) + (w2 + w3);
            __half2 q01 = __floats2half2_rn(w0, w1);
            __half2 q23 = __floats2half2_rn(w2, w3);
            uint32_t u0 = *(uint32_t*)&q01;
            uint32_t u1 = *(uint32_t*)&q23;
            uint32_t o = wbase + row*144 + pc*8;
            asm volatile("st.shared.v2.b32 [%0], {%1,%2};" :: "r"(o), "r"(u0), "r"(u1));
        }
    };

    auto prefetch_adj = [&](int tt) {
        const int tn = (tt < NITER) ? tt*NT : 0;
#pragma unroll
        for (int i = 0; i < 4; i++)
            adjv[i] = __ldg((const int4*)(adjp + (size_t)16*i*MM + tn));
    };

    auto do_mma = [&](int tt) {
        const uint32_t wbase = sbase + (tt & 1)*W_BUF;
        const uint32_t hbase = sbase + SM_H + (tt & 1)*H_BUF;
#pragma unroll
        for (int ks = 0; ks < 4; ks++) {
            uint32_t A0[4], A1[4];
            LDSM4(A0, wbase + offA0 + ks*32);
            LDSM4(A1, wbase + offA1 + ks*32);
#pragma unroll
            for (int fs = 0; fs < 2; fs++) {
                uint32_t B[4];
                LDSM4(B, hbase + offB + fs*(16*144) + ks*32);
                MMAF16(C[0][2*fs],   A0, B[0], B[1]);
                MMAF16(C[0][2*fs+1], A0, B[2], B[3]);
                MMAF16(C[1][2*fs],   A1, B[0], B[1]);
                MMAF16(C[1][2*fs+1], A1, B[2], B[3]);
            }
        }
    };

    stage_h(sbase + SM_H, b, 0, tid);
    build_w(0);
    prefetch_adj(1);
    asm volatile("cp.async.wait_group 0;");
    __syncthreads();

    for (int t = 0; t < NITER; t++) {
        const bool more = (t + 1 < NITER);
        if (more)
            stage_h(sbase + SM_H + ((t+1) & 1)*H_BUF, b, (t+1)*NT, tid);
        if (wid & 1) {
            if (more) { build_w(t+1); prefetch_adj(t+2); }
            do_mma(t);
        } else {
            do_mma(t);
            if (more) { build_w(t+1); prefetch_adj(t+2); }
        }
        if (more)
            asm volatile("cp.async.wait_group 0;");
        __syncthreads();
    }

#pragma unroll
    for (int i = 0; i < 4; i++)
#pragma unroll
        for (int o = 8; o > 0; o >>= 1)
            denp[i] += __shfl_down_sync(0xffffffffu, denp[i], o, 16);
    if (pc == 0) {
#pragma unroll
        for (int i = 0; i < 4; i++) den_s[pr + 16*i] = denp[i];
    }
    __syncthreads();

    float* ob = out + ((size_t)b*MM + m0) * FF;
#pragma unroll
    for (int ms = 0; ms < 2; ms++) {
        const int R0 = wm*32 + ms*16 + (lane >> 2);
        const float inv0 = 1.0f / den_s[R0];
        const float inv1 = 1.0f / den_s[R0 + 8];
#pragma unroll
        for (int j = 0; j < 4; j++) {
            int f0 = wf*32 + j*8 + 2*(lane & 3);
            float e0 = C[ms][j][0] * inv0;
            float e1 = C[ms][j][1] * inv0;
            float e2 = C[ms][j][2] * inv1;
            float e3 = C[ms][j][3] * inv1;
            e0 = e0 > 0.f ? e0 : expm1f(e0);
            e1 = e1 > 0.f ? e1 : expm1f(e1);
            e2 = e2 > 0.f ? e2 : expm1f(e2);
            e3 = e3 > 0.f ? e3 : expm1f(e3);
            *(float2*)(ob + (size_t)R0*FF + f0)     = make_float2(e0, e1);
            *(float2*)(ob + (size_t)(R0+8)*FF + f0) = make_float2(e2, e3);
        }
    }
}

extern "C" void kernel_launch(void* const* d_in, const int* in_sizes, int n_in,
                              void* d_out, int out_size)
{
    const float* x   = (const float*)d_in[0];
    const int*   adj = (const int*)d_in[1];
    const float* W   = (const float*)d_in[2];
    const float* a   = (const float*)d_in[3];
    float*       out = (float*)d_out;

    static int smem_set = 0;
    if (!smem_set) {
        cudaFuncSetAttribute(k_hgemm, cudaFuncAttributeMaxDynamicSharedMemorySize, SM1_TOT);
        cudaFuncSetAttribute(k_attn,  cudaFuncAttributeMaxDynamicSharedMemorySize, SM2_TOT);
        smem_set = 1;
    }

    k_hgemm<<<dim3(MM/64, BB), 256, SM1_TOT>>>(x, W, a);
    k_attn<<<dim3(MM/MT, BB), 256, SM2_TOT>>>(adj, out);
}